// round 15
// baseline (speedup 1.0000x reference)
#include <cuda_runtime.h>
#include <math.h>

#define NA 16384   // atoms
#define NM 1024    // molecules
#define NL 512     // labels
#define NS 1024    // substructures
#define HD 64      // hidden
#define BB 512     // batch
#define SSQ 32     // seq len
#define MAXDEG 128

// ---------------- scratch (device globals; no allocation allowed) -----------
__device__ int   g_cnt[NA];
__device__ int   g_cols[NA * MAXDEG];
__device__ float g_h[NA * HD];      // h1 (layer-0 output)
__device__ float g_h2[NA * HD];     // h2 (layer-1 output)
__device__ float g_mol[NM * HD];
__device__ float g_emb[NL * HD];
__device__ float g_query[BB * HD];
__device__ float g_bipemb[BB * NS];
__device__ float g_bipatt[BB * NL];
__device__ float g_weff[NS * NL];

// ---------------- masked weight: W_eff[s][l] = bo_w[s][l]*mask_H[l][s] ------
__global__ void k_weff(const float* __restrict__ bo_w, const float* __restrict__ mask_H) {
    int i = blockIdx.x * blockDim.x + threadIdx.x;
    if (i < NS * NL) {
        int s = i >> 9, l = i & (NL - 1);
        g_weff[i] = bo_w[i] * mask_H[l * NS + s];
    }
}

// ---------------- bip_emb = query @ bt_w + bt_b (query inlined) -------------
// grid (BB/8, 2): x = batch tile of 8 rows, y = NS half. 512 threads.
__global__ void k_bipemb(const float* __restrict__ queries, const int* __restrict__ vmask,
                         const float* __restrict__ bt_w, const float* __restrict__ bt_b) {
    __shared__ float Qs[8][HD];
    __shared__ int lastv[8];
    int j = threadIdx.x;
    int half = blockIdx.y;
    int b0 = blockIdx.x * 8;
    if (j < 8) {
        const int* vm = vmask + (b0 + j) * SSQ;
        int s = 0;
        #pragma unroll
        for (int t = 0; t < SSQ; t++) s += (vm[t] != 0);
        lastv[j] = (s > 0) ? (s - 1) : 0;
    }
    __syncthreads();
    for (int i = j; i < 8 * HD; i += 512) {
        int r = i >> 6, c = i & 63;
        float q = queries[((long long)(b0 + r) * SSQ + lastv[r]) * HD + c];
        Qs[r][c] = q;
        if (half == 0) g_query[(b0 + r) * HD + c] = q;
    }
    __syncthreads();
    int col = half * 512 + j;
    float acc[8];
    float bz = bt_b[col];
    #pragma unroll
    for (int r = 0; r < 8; r++) acc[r] = bz;
    for (int k = 0; k < HD; k++) {
        float w = bt_w[k * NS + col];
        #pragma unroll
        for (int r = 0; r < 8; r++) acc[r] += Qs[r][k] * w;
    }
    #pragma unroll
    for (int r = 0; r < 8; r++) g_bipemb[(b0 + r) * NS + col] = acc[r];
}

// ---------------- bip_att = bip_emb @ W_eff : register-tiled SGEMM ----------
// M=BB=512, N=NL=512, K=NS=1024. 64x64 tile/block, BK=32, 256 thr, 4x4/thread.
#define BM 64
#define BN 64
#define BK 32
__global__ void k_bipatt() {
    __shared__ float As[BK][BM + 1];   // +1: conflict-free transposed stores
    __shared__ float Bs[BK][BN];
    int tid = threadIdx.x;              // 0..255
    int tx = tid & 15, ty = tid >> 4;   // 16x16 thread grid
    int m0 = blockIdx.y * BM, n0 = blockIdx.x * BN;
    float acc[4][4] = {};
    for (int k0 = 0; k0 < NS; k0 += BK) {
        // A tile 64x32: 2 passes, float4 loads, transposed store
        #pragma unroll
        for (int p = 0; p < 2; p++) {
            int row = p * 32 + (tid >> 3);
            int col = (tid & 7) * 4;
            float4 v = *(const float4*)(g_bipemb + (m0 + row) * NS + k0 + col);
            As[col][row] = v.x; As[col + 1][row] = v.y;
            As[col + 2][row] = v.z; As[col + 3][row] = v.w;
        }
        // B tile 32x64: 2 passes, float4 loads, direct store
        #pragma unroll
        for (int p = 0; p < 2; p++) {
            int row = p * 16 + (tid >> 4);
            int col = (tid & 15) * 4;
            *(float4*)&Bs[row][col] = *(const float4*)(g_weff + (k0 + row) * NL + n0 + col);
        }
        __syncthreads();
        #pragma unroll
        for (int k = 0; k < BK; k++) {
            float ra[4], rb[4];
            #pragma unroll
            for (int i = 0; i < 4; i++) ra[i] = As[k][ty * 4 + i];
            #pragma unroll
            for (int j = 0; j < 4; j++) rb[j] = Bs[k][tx * 4 + j];
            #pragma unroll
            for (int i = 0; i < 4; i++)
                #pragma unroll
                for (int j = 0; j < 4; j++) acc[i][j] += ra[i] * rb[j];
        }
        __syncthreads();
    }
    #pragma unroll
    for (int i = 0; i < 4; i++) {
        float4 v = make_float4(acc[i][0], acc[i][1], acc[i][2], acc[i][3]);
        *(float4*)(g_bipatt + (m0 + ty * 4 + i) * NL + n0 + tx * 4) = v;
    }
}

// ---------------- layer 0: g_h = relu(embed[fp] @ W0 + b0) ------------------
__global__ void k_layer0(const float* __restrict__ W, const float* __restrict__ bias,
                         const int* __restrict__ fp, const float* __restrict__ embed) {
    __shared__ float Ws[HD * HD];
    __shared__ float Xs[4][HD];
    int tid = threadIdx.x;
    for (int i = tid; i < HD * HD; i += 256) Ws[i] = W[i];
    int r = tid >> 6, c = tid & 63;
    int row = blockIdx.x * 4 + r;
    Xs[r][c] = embed[fp[row] * HD + c];
    __syncthreads();
    float acc = bias[c];
    #pragma unroll
    for (int k = 0; k < HD; k++) acc += Xs[r][k] * Ws[k * HD + c];
    g_h[row * HD + c] = fmaxf(acc, 0.f);
}

// ---------------- sparse extraction of adj (1 GiB streaming read) -----------
// adj entries are exactly 0.0/1.0 -> store columns only.
// profiled config: 2048x256, 4 independent uint4 loads/iter, 85% DRAM.
__device__ __forceinline__ void emit_nz(unsigned e) {
    unsigned row = e >> 14;
    unsigned col = e & (NA - 1);
    int slot = atomicAdd(&g_cnt[row], 1);
    if (slot < MAXDEG) g_cols[row * MAXDEG + slot] = (int)col;
}
__device__ __forceinline__ void proc4(uint4 v, unsigned idx4) {
    if ((v.x | v.y | v.z | v.w) != 0u) {
        unsigned e = idx4 * 4u;
        if (v.x) emit_nz(e);
        if (v.y) emit_nz(e + 1);
        if (v.z) emit_nz(e + 2);
        if (v.w) emit_nz(e + 3);
    }
}
__global__ void k_extract(const uint4* __restrict__ adj4) {
    const unsigned TOTAL4 = (unsigned)NA * (NA / 4);   // 2^26
    unsigned stride = gridDim.x * blockDim.x;          // 2048*256 = 2^19
    unsigned i = blockIdx.x * blockDim.x + threadIdx.x;
    for (; i < TOTAL4; i += 4u * stride) {
        uint4 a = __ldcs(&adj4[i]);
        uint4 b = __ldcs(&adj4[i + stride]);
        uint4 c = __ldcs(&adj4[i + 2u * stride]);
        uint4 d = __ldcs(&adj4[i + 3u * stride]);
        proc4(a, i);
        proc4(b, i + stride);
        proc4(c, i + 2u * stride);
        proc4(d, i + 3u * stride);
    }
}

// ---------------- fused: fv1 = h1 + A h1 ; g_h2 = relu(fv1 @ W1 + b1) -------
__global__ void k_layer1_spmv(const float* __restrict__ W, const float* __restrict__ bias) {
    __shared__ float Ws[HD * HD];
    __shared__ float Xs[4][HD];
    int tid = threadIdx.x;
    if (tid < 128) {
        int w = tid >> 5, lane = tid & 31;
        int row = blockIdx.x * 4 + w;
        float a0 = g_h[row * HD + lane];
        float a1 = g_h[row * HD + 32 + lane];
        int cnt = min(g_cnt[row], MAXDEG);
        for (int n = 0; n < cnt; n++) {
            int cc = g_cols[row * MAXDEG + n];
            a0 += g_h[cc * HD + lane];
            a1 += g_h[cc * HD + 32 + lane];
        }
        Xs[w][lane]      = a0;
        Xs[w][32 + lane] = a1;
    } else {
        int t = tid - 128;
        for (int i = t; i < HD * HD; i += 128) Ws[i] = W[i];
    }
    __syncthreads();
    int r = tid >> 6, c = tid & 63;
    int row = blockIdx.x * 4 + r;
    float acc = bias[c];
    #pragma unroll
    for (int k = 0; k < HD; k++) acc += Xs[r][k] * Ws[k * HD + c];
    g_h2[row * HD + c] = fmaxf(acc, 0.f);
}

// ---------------- fused: fv2 = h2 + A h2 ; segment-sum into g_mol -----------
__global__ void k_spmv_seg(const int* __restrict__ seg) {
    int warp = (blockIdx.x * blockDim.x + threadIdx.x) >> 5;
    int lane = threadIdx.x & 31;
    if (warp >= NA) return;
    float a0 = g_h2[warp * HD + lane];
    float a1 = g_h2[warp * HD + 32 + lane];
    int cnt = min(g_cnt[warp], MAXDEG);
    for (int n = 0; n < cnt; n++) {
        int c = g_cols[warp * MAXDEG + n];
        a0 += g_h2[c * HD + lane];
        a1 += g_h2[c * HD + 32 + lane];
    }
    int m = seg[warp];
    atomicAdd(&g_mol[m * HD + lane],      a0);
    atomicAdd(&g_mol[m * HD + 32 + lane], a1);
}

// ---------------- mpnn_emb = avg_proj @ mol ([512,1024]@[1024,64]) ----------
// 128 blocks x 256 threads: 4 labels per block
__global__ void k_avgproj(const float* __restrict__ avg) {
    int r = threadIdx.x >> 6, c = threadIdx.x & 63;
    int l = blockIdx.x * 4 + r;
    const float* arow = avg + l * NM;
    float acc = 0.f;
    #pragma unroll 4
    for (int m = 0; m < NM; m++) acc += arow[m] * g_mol[m * HD + c];
    g_emb[l * HD + c] = acc;
}

// ---------------- fused match/out_w/layernorm/bipatt/sigmoid ----------------
// 4 batch rows per block, 128 blocks, 512 threads (one per label).
// LN stats via E[x^2]-mu^2: one batched two-stage reduction for all 4 rows.
__global__ void k_att_final(const float* __restrict__ out_w, const float* __restrict__ out_b,
                            const float* __restrict__ ln_g, const float* __restrict__ ln_b,
                            float* __restrict__ out) {
    __shared__ float Qs[4][HD];
    __shared__ float Ms[4][NL];
    __shared__ float red[16 * 8];   // [warp][r*2 + {sum,sumsq}]
    __shared__ float red2[8];
    int l = threadIdx.x;
    int b0 = blockIdx.x * 4;
    for (int i = l; i < 4 * HD; i += 512) Qs[i >> 6][i & 63] = g_query[b0 * HD + i];
    __syncthreads();

    float e[HD];
    const float4* er = (const float4*)(g_emb + l * HD);
    #pragma unroll
    for (int k = 0; k < HD / 4; k++) {
        float4 t = er[k];
        e[4 * k] = t.x; e[4 * k + 1] = t.y; e[4 * k + 2] = t.z; e[4 * k + 3] = t.w;
    }
    float m[4];
    #pragma unroll
    for (int r = 0; r < 4; r++) {
        float acc = 0.f;
        #pragma unroll
        for (int k = 0; k < HD; k++) acc += Qs[r][k] * e[k];
        m[r] = 1.f / (1.f + __expf(-acc));
        Ms[r][l] = m[r];
    }
    __syncthreads();

    float acc[4];
    float ob = out_b[l];
    #pragma unroll
    for (int r = 0; r < 4; r++) acc[r] = m[r] + ob;
    for (int k = 0; k < NL; k++) {
        float w = out_w[k * NL + l];
        #pragma unroll
        for (int r = 0; r < 4; r++) acc[r] += Ms[r][k] * w;
    }

    // batched reduction: per-warp (sum, sumsq) for all 4 rows
    int lane = l & 31, wid = l >> 5;
    #pragma unroll
    for (int r = 0; r < 4; r++) {
        float v = acc[r], v2 = acc[r] * acc[r];
        #pragma unroll
        for (int o = 16; o > 0; o >>= 1) {
            v  += __shfl_xor_sync(0xffffffffu, v,  o);
            v2 += __shfl_xor_sync(0xffffffffu, v2, o);
        }
        if (lane == 0) { red[wid * 8 + 2 * r] = v; red[wid * 8 + 2 * r + 1] = v2; }
    }
    __syncthreads();
    if (l < 128) {
        int slot = l & 15, comp = l >> 4;
        float v = red[slot * 8 + comp];
        #pragma unroll
        for (int o = 8; o > 0; o >>= 1) v += __shfl_xor_sync(0xffffffffu, v, o);
        if (slot == 0) red2[comp] = v;
    }
    __syncthreads();

    float gg = ln_g[l], bbv = ln_b[l];
    #pragma unroll
    for (int r = 0; r < 4; r++) {
        float mu  = red2[2 * r]     * (1.f / (float)NL);
        float var = red2[2 * r + 1] * (1.f / (float)NL) - mu * mu;
        float lnv = (acc[r] - mu) * rsqrtf(var + 1e-5f) * gg + bbv;
        float logit = lnv * g_bipatt[(b0 + r) * NL + l];
        out[(b0 + r) * NL + l] = 1.f / (1.f + __expf(-logit));
    }
}

// ---------------- launch ------------------------------------------------------
extern "C" void kernel_launch(void* const* d_in, const int* in_sizes, int n_in,
                              void* d_out, int out_size) {
    const float* queries = (const float*)d_in[0];
    const int*   vmask   = (const int*)d_in[1];
    const float* embed   = (const float*)d_in[2];
    const float* W0w     = (const float*)d_in[3];
    const float* W0b     = (const float*)d_in[4];
    const float* W1w     = (const float*)d_in[5];
    const float* W1b     = (const float*)d_in[6];
    const float* adj     = (const float*)d_in[7];
    const float* avg     = (const float*)d_in[8];
    const float* maskH   = (const float*)d_in[9];
    const float* btw     = (const float*)d_in[10];
    const float* btb     = (const float*)d_in[11];
    const float* bow     = (const float*)d_in[12];
    const float* outw    = (const float*)d_in[13];
    const float* outb    = (const float*)d_in[14];
    const float* lng     = (const float*)d_in[15];
    const float* lnb     = (const float*)d_in[16];
    const int*   fp      = (const int*)d_in[17];
    const int*   seg     = (const int*)d_in[18];
    float*       out     = (float*)d_out;

    // one-time host-side setup (no allocation; identical work every call)
    static cudaStream_t s2 = nullptr;
    static cudaEvent_t evFork = nullptr, evJoin = nullptr;
    static void *p_cnt = nullptr, *p_mol = nullptr;
    if (s2 == nullptr) {
        cudaStreamCreateWithFlags(&s2, cudaStreamNonBlocking);
        cudaEventCreateWithFlags(&evFork, cudaEventDisableTiming);
        cudaEventCreateWithFlags(&evJoin, cudaEventDisableTiming);
        cudaGetSymbolAddress(&p_cnt, g_cnt);
        cudaGetSymbolAddress(&p_mol, g_mol);
    }

    // fork: query path (incl. the bip GEMM) runs concurrently with the adj scan
    cudaEventRecord(evFork, 0);
    cudaStreamWaitEvent(s2, evFork, 0);

    k_layer0<<<NA / 4, 256, 0, s2>>>(W0w, W0b, fp, embed);
    k_bipemb<<<dim3(BB / 8, 2), 512, 0, s2>>>(queries, vmask, btw, btb);
    k_weff  <<<(NS * NL) / 256, 256, 0, s2>>>(bow, maskH);
    k_bipatt<<<dim3(NL / BN, BB / BM), 256, 0, s2>>>();
    cudaEventRecord(evJoin, s2);

    // main: zero (memset nodes) + CSR build (dominant, ~160us @ 85% DRAM)
    cudaMemsetAsync(p_cnt, 0, NA * sizeof(int), 0);
    cudaMemsetAsync(p_mol, 0, NM * HD * sizeof(float), 0);
    k_extract<<<2048, 256>>>((const uint4*)adj);

    // join: layer1 needs g_h (s2) + CSR (main); att_final needs g_bipatt (s2)
    cudaStreamWaitEvent(0, evJoin, 0);

    k_layer1_spmv<<<NA / 4, 256>>>(W1w, W1b);
    k_spmv_seg   <<<(NA * 32) / 256, 256>>>(seg);
    k_avgproj    <<<NL / 4, 256>>>(avg);
    k_att_final  <<<BB / 4, 512>>>(outw, outb, lng, lnb, out);
}

// round 16
// speedup vs baseline: 1.2613x; 1.2613x over previous
#include <cuda_runtime.h>
#include <math.h>

#define NA 16384   // atoms
#define NM 1024    // molecules
#define NL 512     // labels
#define NS 1024    // substructures
#define HD 64      // hidden
#define BB 512     // batch
#define SSQ 32     // seq len
#define MAXDEG 128

// ---------------- scratch (device globals; no allocation allowed) -----------
__device__ int   g_cnt[NA];
__device__ int   g_cols[NA * MAXDEG];
__device__ float g_h[NA * HD];      // h1 (layer-0 output)
__device__ float g_h2[NA * HD];     // h2 (layer-1 output)
__device__ float g_mol[NM * HD];
__device__ float g_emb[NL * HD];
__device__ float g_query[BB * HD];
__device__ float g_bipemb[BB * NS];
__device__ float g_bipatt[BB * NL];
__device__ float g_weff[NS * NL];

// ---------------- masked weight: W_eff[s][l] = bo_w[s][l]*mask_H[l][s] ------
__global__ void k_weff(const float* __restrict__ bo_w, const float* __restrict__ mask_H) {
    int i = blockIdx.x * blockDim.x + threadIdx.x;
    if (i < NS * NL) {
        int s = i >> 9, l = i & (NL - 1);
        g_weff[i] = bo_w[i] * mask_H[l * NS + s];
    }
}

// ---------------- bip_emb = query @ bt_w + bt_b (query inlined) -------------
// grid (BB/8, 2): x = batch tile of 8 rows, y = NS half. 512 threads.
__global__ void k_bipemb(const float* __restrict__ queries, const int* __restrict__ vmask,
                         const float* __restrict__ bt_w, const float* __restrict__ bt_b) {
    __shared__ float Qs[8][HD];
    __shared__ int lastv[8];
    int j = threadIdx.x;
    int half = blockIdx.y;
    int b0 = blockIdx.x * 8;
    if (j < 8) {
        const int* vm = vmask + (b0 + j) * SSQ;
        int s = 0;
        #pragma unroll
        for (int t = 0; t < SSQ; t++) s += (vm[t] != 0);
        lastv[j] = (s > 0) ? (s - 1) : 0;
    }
    __syncthreads();
    for (int i = j; i < 8 * HD; i += 512) {
        int r = i >> 6, c = i & 63;
        float q = queries[((long long)(b0 + r) * SSQ + lastv[r]) * HD + c];
        Qs[r][c] = q;
        if (half == 0) g_query[(b0 + r) * HD + c] = q;
    }
    __syncthreads();
    int col = half * 512 + j;
    float acc[8];
    float bz = bt_b[col];
    #pragma unroll
    for (int r = 0; r < 8; r++) acc[r] = bz;
    for (int k = 0; k < HD; k++) {
        float w = bt_w[k * NS + col];
        #pragma unroll
        for (int r = 0; r < 8; r++) acc[r] += Qs[r][k] * w;
    }
    #pragma unroll
    for (int r = 0; r < 8; r++) g_bipemb[(b0 + r) * NS + col] = acc[r];
}

// ---------------- bip_att = bip_emb @ W_eff : register-tiled SGEMM ----------
// M=512, N=512, K=1024. 32x32 tile/block (256 blocks -> full-chip), BK=32,
// 256 threads, 2x2 accumulators/thread.
#define BM 32
#define BN 32
#define BK 32
__global__ void k_bipatt() {
    __shared__ float As[BK][BM + 1];   // transposed store, +1 pad
    __shared__ float Bs[BK][BN];
    int tid = threadIdx.x;              // 0..255
    int tx = tid & 15, ty = tid >> 4;   // 16x16 thread grid
    int m0 = blockIdx.y * BM, n0 = blockIdx.x * BN;
    float acc[2][2] = {};
    for (int k0 = 0; k0 < NS; k0 += BK) {
        // A tile 32x32: one float4 per thread, transposed store
        {
            int row = tid >> 3;          // 0..31
            int col = (tid & 7) * 4;     // 0..28
            float4 v = *(const float4*)(g_bipemb + (m0 + row) * NS + k0 + col);
            As[col][row] = v.x; As[col + 1][row] = v.y;
            As[col + 2][row] = v.z; As[col + 3][row] = v.w;
        }
        // B tile 32x32: one float4 per thread, direct store
        {
            int row = tid >> 3;
            int col = (tid & 7) * 4;
            *(float4*)&Bs[row][col] = *(const float4*)(g_weff + (k0 + row) * NL + n0 + col);
        }
        __syncthreads();
        #pragma unroll
        for (int k = 0; k < BK; k++) {
            float a0 = As[k][ty * 2], a1 = As[k][ty * 2 + 1];
            float b0 = Bs[k][tx * 2], b1 = Bs[k][tx * 2 + 1];
            acc[0][0] += a0 * b0; acc[0][1] += a0 * b1;
            acc[1][0] += a1 * b0; acc[1][1] += a1 * b1;
        }
        __syncthreads();
    }
    #pragma unroll
    for (int i = 0; i < 2; i++) {
        float2 v = make_float2(acc[i][0], acc[i][1]);
        *(float2*)(g_bipatt + (m0 + ty * 2 + i) * NL + n0 + tx * 2) = v;
    }
}

// ---------------- layer 0: g_h = relu(embed[fp] @ W0 + b0) ------------------
__global__ void k_layer0(const float* __restrict__ W, const float* __restrict__ bias,
                         const int* __restrict__ fp, const float* __restrict__ embed) {
    __shared__ float Ws[HD * HD];
    __shared__ float Xs[4][HD];
    int tid = threadIdx.x;
    for (int i = tid; i < HD * HD; i += 256) Ws[i] = W[i];
    int r = tid >> 6, c = tid & 63;
    int row = blockIdx.x * 4 + r;
    Xs[r][c] = embed[fp[row] * HD + c];
    __syncthreads();
    float acc = bias[c];
    #pragma unroll
    for (int k = 0; k < HD; k++) acc += Xs[r][k] * Ws[k * HD + c];
    g_h[row * HD + c] = fmaxf(acc, 0.f);
}

// ---------------- sparse extraction of adj (1 GiB streaming read) -----------
// adj entries are exactly 0.0/1.0 -> store columns only.
// profiled config: 2048x256, 4 independent uint4 loads/iter, 85% DRAM.
__device__ __forceinline__ void emit_nz(unsigned e) {
    unsigned row = e >> 14;
    unsigned col = e & (NA - 1);
    int slot = atomicAdd(&g_cnt[row], 1);
    if (slot < MAXDEG) g_cols[row * MAXDEG + slot] = (int)col;
}
__device__ __forceinline__ void proc4(uint4 v, unsigned idx4) {
    if ((v.x | v.y | v.z | v.w) != 0u) {
        unsigned e = idx4 * 4u;
        if (v.x) emit_nz(e);
        if (v.y) emit_nz(e + 1);
        if (v.z) emit_nz(e + 2);
        if (v.w) emit_nz(e + 3);
    }
}
__global__ void k_extract(const uint4* __restrict__ adj4) {
    const unsigned TOTAL4 = (unsigned)NA * (NA / 4);   // 2^26
    unsigned stride = gridDim.x * blockDim.x;          // 2048*256 = 2^19
    unsigned i = blockIdx.x * blockDim.x + threadIdx.x;
    for (; i < TOTAL4; i += 4u * stride) {
        uint4 a = __ldcs(&adj4[i]);
        uint4 b = __ldcs(&adj4[i + stride]);
        uint4 c = __ldcs(&adj4[i + 2u * stride]);
        uint4 d = __ldcs(&adj4[i + 3u * stride]);
        proc4(a, i);
        proc4(b, i + stride);
        proc4(c, i + 2u * stride);
        proc4(d, i + 3u * stride);
    }
}

// ---------------- fused: fv1 = h1 + A h1 ; g_h2 = relu(fv1 @ W1 + b1) -------
__global__ void k_layer1_spmv(const float* __restrict__ W, const float* __restrict__ bias) {
    __shared__ float Ws[HD * HD];
    __shared__ float Xs[4][HD];
    int tid = threadIdx.x;
    if (tid < 128) {
        int w = tid >> 5, lane = tid & 31;
        int row = blockIdx.x * 4 + w;
        float a0 = g_h[row * HD + lane];
        float a1 = g_h[row * HD + 32 + lane];
        int cnt = min(g_cnt[row], MAXDEG);
        for (int n = 0; n < cnt; n++) {
            int cc = g_cols[row * MAXDEG + n];
            a0 += g_h[cc * HD + lane];
            a1 += g_h[cc * HD + 32 + lane];
        }
        Xs[w][lane]      = a0;
        Xs[w][32 + lane] = a1;
    } else {
        int t = tid - 128;
        for (int i = t; i < HD * HD; i += 128) Ws[i] = W[i];
    }
    __syncthreads();
    int r = tid >> 6, c = tid & 63;
    int row = blockIdx.x * 4 + r;
    float acc = bias[c];
    #pragma unroll
    for (int k = 0; k < HD; k++) acc += Xs[r][k] * Ws[k * HD + c];
    g_h2[row * HD + c] = fmaxf(acc, 0.f);
}

// ---------------- fused: fv2 = h2 + A h2 ; segment-sum into g_mol -----------
__global__ void k_spmv_seg(const int* __restrict__ seg) {
    int warp = (blockIdx.x * blockDim.x + threadIdx.x) >> 5;
    int lane = threadIdx.x & 31;
    if (warp >= NA) return;
    float a0 = g_h2[warp * HD + lane];
    float a1 = g_h2[warp * HD + 32 + lane];
    int cnt = min(g_cnt[warp], MAXDEG);
    for (int n = 0; n < cnt; n++) {
        int c = g_cols[warp * MAXDEG + n];
        a0 += g_h2[c * HD + lane];
        a1 += g_h2[c * HD + 32 + lane];
    }
    int m = seg[warp];
    atomicAdd(&g_mol[m * HD + lane],      a0);
    atomicAdd(&g_mol[m * HD + 32 + lane], a1);
}

// ---------------- mpnn_emb = avg_proj @ mol ([512,1024]@[1024,64]) ----------
// 128 blocks x 256 threads: 4 labels per block
__global__ void k_avgproj(const float* __restrict__ avg) {
    int r = threadIdx.x >> 6, c = threadIdx.x & 63;
    int l = blockIdx.x * 4 + r;
    const float* arow = avg + l * NM;
    float acc = 0.f;
    #pragma unroll 4
    for (int m = 0; m < NM; m++) acc += arow[m] * g_mol[m * HD + c];
    g_emb[l * HD + c] = acc;
}

// ---------------- fused match/out_w/layernorm/bipatt/sigmoid ----------------
// 4 batch rows per block, 128 blocks, 512 threads (one per label).
// LN stats via E[x^2]-mu^2: one batched two-stage reduction for all 4 rows.
__global__ void k_att_final(const float* __restrict__ out_w, const float* __restrict__ out_b,
                            const float* __restrict__ ln_g, const float* __restrict__ ln_b,
                            float* __restrict__ out) {
    __shared__ float Qs[4][HD];
    __shared__ float Ms[4][NL];
    __shared__ float red[16 * 8];   // [warp][r*2 + {sum,sumsq}]
    __shared__ float red2[8];
    int l = threadIdx.x;
    int b0 = blockIdx.x * 4;
    for (int i = l; i < 4 * HD; i += 512) Qs[i >> 6][i & 63] = g_query[b0 * HD + i];
    __syncthreads();

    float e[HD];
    const float4* er = (const float4*)(g_emb + l * HD);
    #pragma unroll
    for (int k = 0; k < HD / 4; k++) {
        float4 t = er[k];
        e[4 * k] = t.x; e[4 * k + 1] = t.y; e[4 * k + 2] = t.z; e[4 * k + 3] = t.w;
    }
    float m[4];
    #pragma unroll
    for (int r = 0; r < 4; r++) {
        float acc = 0.f;
        #pragma unroll
        for (int k = 0; k < HD; k++) acc += Qs[r][k] * e[k];
        m[r] = 1.f / (1.f + __expf(-acc));
        Ms[r][l] = m[r];
    }
    __syncthreads();

    float acc[4];
    float ob = out_b[l];
    #pragma unroll
    for (int r = 0; r < 4; r++) acc[r] = m[r] + ob;
    for (int k = 0; k < NL; k++) {
        float w = out_w[k * NL + l];
        #pragma unroll
        for (int r = 0; r < 4; r++) acc[r] += Ms[r][k] * w;
    }

    // batched reduction: per-warp (sum, sumsq) for all 4 rows
    int lane = l & 31, wid = l >> 5;
    #pragma unroll
    for (int r = 0; r < 4; r++) {
        float v = acc[r], v2 = acc[r] * acc[r];
        #pragma unroll
        for (int o = 16; o > 0; o >>= 1) {
            v  += __shfl_xor_sync(0xffffffffu, v,  o);
            v2 += __shfl_xor_sync(0xffffffffu, v2, o);
        }
        if (lane == 0) { red[wid * 8 + 2 * r] = v; red[wid * 8 + 2 * r + 1] = v2; }
    }
    __syncthreads();
    if (l < 128) {
        int slot = l & 15, comp = l >> 4;
        float v = red[slot * 8 + comp];
        #pragma unroll
        for (int o = 8; o > 0; o >>= 1) v += __shfl_xor_sync(0xffffffffu, v, o);
        if (slot == 0) red2[comp] = v;
    }
    __syncthreads();

    float gg = ln_g[l], bbv = ln_b[l];
    #pragma unroll
    for (int r = 0; r < 4; r++) {
        float mu  = red2[2 * r]     * (1.f / (float)NL);
        float var = red2[2 * r + 1] * (1.f / (float)NL) - mu * mu;
        float lnv = (acc[r] - mu) * rsqrtf(var + 1e-5f) * gg + bbv;
        float logit = lnv * g_bipatt[(b0 + r) * NL + l];
        out[(b0 + r) * NL + l] = 1.f / (1.f + __expf(-logit));
    }
}

// ---------------- launch ------------------------------------------------------
extern "C" void kernel_launch(void* const* d_in, const int* in_sizes, int n_in,
                              void* d_out, int out_size) {
    const float* queries = (const float*)d_in[0];
    const int*   vmask   = (const int*)d_in[1];
    const float* embed   = (const float*)d_in[2];
    const float* W0w     = (const float*)d_in[3];
    const float* W0b     = (const float*)d_in[4];
    const float* W1w     = (const float*)d_in[5];
    const float* W1b     = (const float*)d_in[6];
    const float* adj     = (const float*)d_in[7];
    const float* avg     = (const float*)d_in[8];
    const float* maskH   = (const float*)d_in[9];
    const float* btw     = (const float*)d_in[10];
    const float* btb     = (const float*)d_in[11];
    const float* bow     = (const float*)d_in[12];
    const float* outw    = (const float*)d_in[13];
    const float* outb    = (const float*)d_in[14];
    const float* lng     = (const float*)d_in[15];
    const float* lnb     = (const float*)d_in[16];
    const int*   fp      = (const int*)d_in[17];
    const int*   seg     = (const int*)d_in[18];
    float*       out     = (float*)d_out;

    // one-time symbol address lookup (no allocation; identical work every call)
    static void *p_cnt = nullptr, *p_mol = nullptr;
    if (p_cnt == nullptr) {
        cudaGetSymbolAddress(&p_cnt, g_cnt);
        cudaGetSymbolAddress(&p_mol, g_mol);
    }

    // sequential single-stream pipeline (stream fork measured as a regression:
    // R14 410 -> R15 462 with a SHORTER forked leg; graph cross-stream edges
    // cost more than the overlap saves on this BW-bound workload)
    cudaMemsetAsync(p_cnt, 0, NA * sizeof(int), 0);
    cudaMemsetAsync(p_mol, 0, NM * HD * sizeof(float), 0);

    k_layer0     <<<NA / 4, 256>>>(W0w, W0b, fp, embed);               // k0
    k_bipemb     <<<dim3(BB / 8, 2), 512>>>(queries, vmask, btw, btb); // k1
    k_weff       <<<(NS * NL) / 256, 256>>>(bow, maskH);               // k2
    k_bipatt     <<<dim3(NL / BN, BB / BM), 256>>>();                  // k3
    k_extract    <<<2048, 256>>>((const uint4*)adj);                   // k4
    k_layer1_spmv<<<NA / 4, 256>>>(W1w, W1b);                          // k5 <- ncu window
    k_spmv_seg   <<<(NA * 32) / 256, 256>>>(seg);                      // k6
    k_avgproj    <<<NL / 4, 256>>>(avg);                               // k7
    k_att_final  <<<BB / 4, 512>>>(outw, outb, lng, lnb, out);         // k8
}

// round 17
// speedup vs baseline: 1.3358x; 1.0591x over previous
#include <cuda_runtime.h>
#include <math.h>

#define NA 16384   // atoms
#define NM 1024    // molecules
#define NL 512     // labels
#define NS 1024    // substructures
#define HD 64      // hidden
#define BB 512     // batch
#define SSQ 32     // seq len
#define MAXDEG 128

#define BM 64
#define BN 64
#define BK 16
#define KSPLIT 4

// ---------------- scratch (device globals; no allocation allowed) -----------
__device__ int   g_cnt[NA];
__device__ int   g_cols[NA * MAXDEG];
__device__ float g_h[NA * HD];      // h1 (layer-0 output)
__device__ float g_h2[NA * HD];     // h2 (layer-1 output)
__device__ float g_mol[NM * HD];
__device__ float g_emb[NL * HD];
__device__ float g_query[BB * HD];
__device__ float g_bipemb[BB * NS];
__device__ float g_bipatt4[KSPLIT][BB * NL];   // split-K partials
__device__ float g_weff[NS * NL];

// ---------------- masked weight: W_eff[s][l] = bo_w[s][l]*mask_H[l][s] ------
__global__ void k_weff(const float* __restrict__ bo_w, const float* __restrict__ mask_H) {
    int i = blockIdx.x * blockDim.x + threadIdx.x;
    if (i < NS * NL) {
        int s = i >> 9, l = i & (NL - 1);
        g_weff[i] = bo_w[i] * mask_H[l * NS + s];
    }
}

// ---------------- bip_emb = query @ bt_w + bt_b (query inlined) -------------
// grid (BB/8, 2): x = batch tile of 8 rows, y = NS half. 512 threads.
__global__ void k_bipemb(const float* __restrict__ queries, const int* __restrict__ vmask,
                         const float* __restrict__ bt_w, const float* __restrict__ bt_b) {
    __shared__ float Qs[8][HD];
    __shared__ int lastv[8];
    int j = threadIdx.x;
    int half = blockIdx.y;
    int b0 = blockIdx.x * 8;
    if (j < 8) {
        const int* vm = vmask + (b0 + j) * SSQ;
        int s = 0;
        #pragma unroll
        for (int t = 0; t < SSQ; t++) s += (vm[t] != 0);
        lastv[j] = (s > 0) ? (s - 1) : 0;
    }
    __syncthreads();
    for (int i = j; i < 8 * HD; i += 512) {
        int r = i >> 6, c = i & 63;
        float q = queries[((long long)(b0 + r) * SSQ + lastv[r]) * HD + c];
        Qs[r][c] = q;
        if (half == 0) g_query[(b0 + r) * HD + c] = q;
    }
    __syncthreads();
    int col = half * 512 + j;
    float acc[8];
    float bz = bt_b[col];
    #pragma unroll
    for (int r = 0; r < 8; r++) acc[r] = bz;
    for (int k = 0; k < HD; k++) {
        float w = bt_w[k * NS + col];
        #pragma unroll
        for (int r = 0; r < 8; r++) acc[r] += Qs[r][k] * w;
    }
    #pragma unroll
    for (int r = 0; r < 8; r++) g_bipemb[(b0 + r) * NS + col] = acc[r];
}

// ---------------- bip_att partials: split-K register-tiled SGEMM ------------
// M=N=512, K=1024. 64x64 tile, BK=16, split-K x4 -> grid (8,8,4) = 256 blocks.
// 256 threads, 4x4 acc/thread, float4 LDS reads: 2 B/FMA smem traffic.
__global__ void k_bipatt() {
    __shared__ __align__(16) float As[BK][BM + 4];  // transposed, padded
    __shared__ __align__(16) float Bs[BK][BN];
    int tid = threadIdx.x;              // 0..255
    int tx = tid & 15, ty = tid >> 4;   // 16x16 thread grid
    int n0 = blockIdx.x * BN, m0 = blockIdx.y * BM;
    int kbeg = blockIdx.z * (NS / KSPLIT);
    float acc[4][4] = {};
    for (int kt = 0; kt < NS / KSPLIT; kt += BK) {
        int k0 = kbeg + kt;
        {   // A tile 64x16: one float4/thread, transposed store
            int row = tid >> 2;          // 0..63
            int col = (tid & 3) * 4;     // 0..12
            float4 v = *(const float4*)(g_bipemb + (m0 + row) * NS + k0 + col);
            As[col][row] = v.x; As[col + 1][row] = v.y;
            As[col + 2][row] = v.z; As[col + 3][row] = v.w;
        }
        {   // B tile 16x64: one float4/thread, direct store
            int row = tid >> 4;          // 0..15
            int col = (tid & 15) * 4;    // 0..60
            *(float4*)&Bs[row][col] = *(const float4*)(g_weff + (k0 + row) * NL + n0 + col);
        }
        __syncthreads();
        #pragma unroll
        for (int k = 0; k < BK; k++) {
            float4 ra = *(const float4*)&As[k][ty * 4];
            float4 rb = *(const float4*)&Bs[k][tx * 4];
            acc[0][0] += ra.x * rb.x; acc[0][1] += ra.x * rb.y;
            acc[0][2] += ra.x * rb.z; acc[0][3] += ra.x * rb.w;
            acc[1][0] += ra.y * rb.x; acc[1][1] += ra.y * rb.y;
            acc[1][2] += ra.y * rb.z; acc[1][3] += ra.y * rb.w;
            acc[2][0] += ra.z * rb.x; acc[2][1] += ra.z * rb.y;
            acc[2][2] += ra.z * rb.z; acc[2][3] += ra.z * rb.w;
            acc[3][0] += ra.w * rb.x; acc[3][1] += ra.w * rb.y;
            acc[3][2] += ra.w * rb.z; acc[3][3] += ra.w * rb.w;
        }
        __syncthreads();
    }
    float* dst = g_bipatt4[blockIdx.z];
    #pragma unroll
    for (int i = 0; i < 4; i++) {
        float4 v = make_float4(acc[i][0], acc[i][1], acc[i][2], acc[i][3]);
        *(float4*)(dst + (m0 + ty * 4 + i) * NL + n0 + tx * 4) = v;
    }
}

// ---------------- layer 0: g_h = relu(embed[fp] @ W0 + b0) ------------------
__global__ void k_layer0(const float* __restrict__ W, const float* __restrict__ bias,
                         const int* __restrict__ fp, const float* __restrict__ embed) {
    __shared__ float Ws[HD * HD];
    __shared__ float Xs[4][HD];
    int tid = threadIdx.x;
    for (int i = tid; i < HD * HD; i += 256) Ws[i] = W[i];
    int r = tid >> 6, c = tid & 63;
    int row = blockIdx.x * 4 + r;
    Xs[r][c] = embed[fp[row] * HD + c];
    __syncthreads();
    float acc = bias[c];
    #pragma unroll
    for (int k = 0; k < HD; k++) acc += Xs[r][k] * Ws[k * HD + c];
    g_h[row * HD + c] = fmaxf(acc, 0.f);
}

// ---------------- sparse extraction of adj (1 GiB streaming read) -----------
// adj entries are exactly 0.0/1.0 -> store columns only.
// profiled config: 2048x256, 4 independent uint4 loads/iter, 85% DRAM.
__device__ __forceinline__ void emit_nz(unsigned e) {
    unsigned row = e >> 14;
    unsigned col = e & (NA - 1);
    int slot = atomicAdd(&g_cnt[row], 1);
    if (slot < MAXDEG) g_cols[row * MAXDEG + slot] = (int)col;
}
__device__ __forceinline__ void proc4(uint4 v, unsigned idx4) {
    if ((v.x | v.y | v.z | v.w) != 0u) {
        unsigned e = idx4 * 4u;
        if (v.x) emit_nz(e);
        if (v.y) emit_nz(e + 1);
        if (v.z) emit_nz(e + 2);
        if (v.w) emit_nz(e + 3);
    }
}
__global__ void k_extract(const uint4* __restrict__ adj4) {
    const unsigned TOTAL4 = (unsigned)NA * (NA / 4);   // 2^26
    unsigned stride = gridDim.x * blockDim.x;          // 2048*256 = 2^19
    unsigned i = blockIdx.x * blockDim.x + threadIdx.x;
    for (; i < TOTAL4; i += 4u * stride) {
        uint4 a = __ldcs(&adj4[i]);
        uint4 b = __ldcs(&adj4[i + stride]);
        uint4 c = __ldcs(&adj4[i + 2u * stride]);
        uint4 d = __ldcs(&adj4[i + 3u * stride]);
        proc4(a, i);
        proc4(b, i + stride);
        proc4(c, i + 2u * stride);
        proc4(d, i + 3u * stride);
    }
}

// ---------------- fused: fv1 = h1 + A h1 ; g_h2 = relu(fv1 @ W1 + b1) -------
__global__ void k_layer1_spmv(const float* __restrict__ W, const float* __restrict__ bias) {
    __shared__ float Ws[HD * HD];
    __shared__ float Xs[4][HD];
    int tid = threadIdx.x;
    if (tid < 128) {
        int w = tid >> 5, lane = tid & 31;
        int row = blockIdx.x * 4 + w;
        float a0 = g_h[row * HD + lane];
        float a1 = g_h[row * HD + 32 + lane];
        int cnt = min(g_cnt[row], MAXDEG);
        for (int n = 0; n < cnt; n++) {
            int cc = g_cols[row * MAXDEG + n];
            a0 += g_h[cc * HD + lane];
            a1 += g_h[cc * HD + 32 + lane];
        }
        Xs[w][lane]      = a0;
        Xs[w][32 + lane] = a1;
    } else {
        int t = tid - 128;
        for (int i = t; i < HD * HD; i += 128) Ws[i] = W[i];
    }
    __syncthreads();
    int r = tid >> 6, c = tid & 63;
    int row = blockIdx.x * 4 + r;
    float acc = bias[c];
    #pragma unroll
    for (int k = 0; k < HD; k++) acc += Xs[r][k] * Ws[k * HD + c];
    g_h2[row * HD + c] = fmaxf(acc, 0.f);
}

// ---------------- fused: fv2 = h2 + A h2 ; segment-sum into g_mol -----------
__global__ void k_spmv_seg(const int* __restrict__ seg) {
    int warp = (blockIdx.x * blockDim.x + threadIdx.x) >> 5;
    int lane = threadIdx.x & 31;
    if (warp >= NA) return;
    float a0 = g_h2[warp * HD + lane];
    float a1 = g_h2[warp * HD + 32 + lane];
    int cnt = min(g_cnt[warp], MAXDEG);
    for (int n = 0; n < cnt; n++) {
        int c = g_cols[warp * MAXDEG + n];
        a0 += g_h2[c * HD + lane];
        a1 += g_h2[c * HD + 32 + lane];
    }
    int m = seg[warp];
    atomicAdd(&g_mol[m * HD + lane],      a0);
    atomicAdd(&g_mol[m * HD + 32 + lane], a1);
}

// ---------------- mpnn_emb = avg_proj @ mol ([512,1024]@[1024,64]) ----------
// 128 blocks x 256 threads: 4 labels per block
__global__ void k_avgproj(const float* __restrict__ avg) {
    int r = threadIdx.x >> 6, c = threadIdx.x & 63;
    int l = blockIdx.x * 4 + r;
    const float* arow = avg + l * NM;
    float acc = 0.f;
    #pragma unroll 4
    for (int m = 0; m < NM; m++) acc += arow[m] * g_mol[m * HD + c];
    g_emb[l * HD + c] = acc;
}

// ---------------- fused match/out_w/layernorm/bipatt-sum/sigmoid ------------
// 4 batch rows per block, 128 blocks, 512 threads (one per label).
__global__ void k_att_final(const float* __restrict__ out_w, const float* __restrict__ out_b,
                            const float* __restrict__ ln_g, const float* __restrict__ ln_b,
                            float* __restrict__ out) {
    __shared__ float Qs[4][HD];
    __shared__ float Ms[4][NL];
    __shared__ float red[16 * 8];   // [warp][r*2 + {sum,sumsq}]
    __shared__ float red2[8];
    int l = threadIdx.x;
    int b0 = blockIdx.x * 4;
    for (int i = l; i < 4 * HD; i += 512) Qs[i >> 6][i & 63] = g_query[b0 * HD + i];
    __syncthreads();

    float e[HD];
    const float4* er = (const float4*)(g_emb + l * HD);
    #pragma unroll
    for (int k = 0; k < HD / 4; k++) {
        float4 t = er[k];
        e[4 * k] = t.x; e[4 * k + 1] = t.y; e[4 * k + 2] = t.z; e[4 * k + 3] = t.w;
    }
    float m[4];
    #pragma unroll
    for (int r = 0; r < 4; r++) {
        float acc = 0.f;
        #pragma unroll
        for (int k = 0; k < HD; k++) acc += Qs[r][k] * e[k];
        m[r] = 1.f / (1.f + __expf(-acc));
        Ms[r][l] = m[r];
    }
    __syncthreads();

    float acc[4];
    float ob = out_b[l];
    #pragma unroll
    for (int r = 0; r < 4; r++) acc[r] = m[r] + ob;
    for (int k = 0; k < NL; k++) {
        float w = out_w[k * NL + l];
        #pragma unroll
        for (int r = 0; r < 4; r++) acc[r] += Ms[r][k] * w;
    }

    // batched reduction: per-warp (sum, sumsq) for all 4 rows
    int lane = l & 31, wid = l >> 5;
    #pragma unroll
    for (int r = 0; r < 4; r++) {
        float v = acc[r], v2 = acc[r] * acc[r];
        #pragma unroll
        for (int o = 16; o > 0; o >>= 1) {
            v  += __shfl_xor_sync(0xffffffffu, v,  o);
            v2 += __shfl_xor_sync(0xffffffffu, v2, o);
        }
        if (lane == 0) { red[wid * 8 + 2 * r] = v; red[wid * 8 + 2 * r + 1] = v2; }
    }
    __syncthreads();
    if (l < 128) {
        int slot = l & 15, comp = l >> 4;
        float v = red[slot * 8 + comp];
        #pragma unroll
        for (int o = 8; o > 0; o >>= 1) v += __shfl_xor_sync(0xffffffffu, v, o);
        if (slot == 0) red2[comp] = v;
    }
    __syncthreads();

    float gg = ln_g[l], bbv = ln_b[l];
    #pragma unroll
    for (int r = 0; r < 4; r++) {
        float mu  = red2[2 * r]     * (1.f / (float)NL);
        float var = red2[2 * r + 1] * (1.f / (float)NL) - mu * mu;
        float lnv = (acc[r] - mu) * rsqrtf(var + 1e-5f) * gg + bbv;
        int idx = (b0 + r) * NL + l;
        float bip = g_bipatt4[0][idx] + g_bipatt4[1][idx]
                  + g_bipatt4[2][idx] + g_bipatt4[3][idx];
        float logit = lnv * bip;
        out[idx] = 1.f / (1.f + __expf(-logit));
    }
}

// ---------------- launch ------------------------------------------------------
extern "C" void kernel_launch(void* const* d_in, const int* in_sizes, int n_in,
                              void* d_out, int out_size) {
    const float* queries = (const float*)d_in[0];
    const int*   vmask   = (const int*)d_in[1];
    const float* embed   = (const float*)d_in[2];
    const float* W0w     = (const float*)d_in[3];
    const float* W0b     = (const float*)d_in[4];
    const float* W1w     = (const float*)d_in[5];
    const float* W1b     = (const float*)d_in[6];
    const float* adj     = (const float*)d_in[7];
    const float* avg     = (const float*)d_in[8];
    const float* maskH   = (const float*)d_in[9];
    const float* btw     = (const float*)d_in[10];
    const float* btb     = (const float*)d_in[11];
    const float* bow     = (const float*)d_in[12];
    const float* outw    = (const float*)d_in[13];
    const float* outb    = (const float*)d_in[14];
    const float* lng     = (const float*)d_in[15];
    const float* lnb     = (const float*)d_in[16];
    const int*   fp      = (const int*)d_in[17];
    const int*   seg     = (const int*)d_in[18];
    float*       out     = (float*)d_out;

    // one-time symbol address lookup (no allocation; identical work every call)
    static void *p_cnt = nullptr, *p_mol = nullptr;
    if (p_cnt == nullptr) {
        cudaGetSymbolAddress(&p_cnt, g_cnt);
        cudaGetSymbolAddress(&p_mol, g_mol);
    }

    // sequential single-stream pipeline. Order puts k_layer1_spmv at ncu's
    // capture position 5 (2 memsets + 3 kernels precede it).
    cudaMemsetAsync(p_cnt, 0, NA * sizeof(int), 0);                    // 0
    cudaMemsetAsync(p_mol, 0, NM * HD * sizeof(float), 0);             // 1
    k_layer0     <<<NA / 4, 256>>>(W0w, W0b, fp, embed);               // 2
    k_extract    <<<2048, 256>>>((const uint4*)adj);                   // 3
    k_bipemb     <<<dim3(BB / 8, 2), 512>>>(queries, vmask, btw, btb); // 4
    k_layer1_spmv<<<NA / 4, 256>>>(W1w, W1b);                          // 5 <- ncu
    k_weff       <<<(NS * NL) / 256, 256>>>(bow, maskH);               // 6
    k_bipatt     <<<dim3(NL / BN, BB / BM, KSPLIT), 256>>>();          // 7
    k_spmv_seg   <<<(NA * 32) / 256, 256>>>(seg);                      // 8
    k_avgproj    <<<NL / 4, 256>>>(avg);                               // 9
    k_att_final  <<<BB / 4, 512>>>(outw, outb, lng, lnb, out);         // 10
}